// round 6
// baseline (speedup 1.0000x reference)
#include <cuda_runtime.h>

#define B_    2
#define N_    512
#define E_    768
#define H_    48
#define D_    16
#define NEXP_ 256
#define M_    768
#define LOG2E 1.4426950408889634f

typedef unsigned long long ull;

__device__ __forceinline__ ull pk2(float lo, float hi){ ull r; asm("mov.b64 %0,{%1,%2};":"=l"(r):"f"(lo),"f"(hi)); return r; }
__device__ __forceinline__ void upk2(float&lo,float&hi,ull v){ asm("mov.b64 {%0,%1},%2;":"=f"(lo),"=f"(hi):"l"(v)); }
__device__ __forceinline__ ull fma2_(ull a, ull b, ull c){ ull d; asm("fma.rn.f32x2 %0,%1,%2,%3;":"=l"(d):"l"(a),"l"(b),"l"(c)); return d; }
__device__ __forceinline__ ull add2_(ull a, ull b){ ull d; asm("add.rn.f32x2 %0,%1,%2;":"=l"(d):"l"(a),"l"(b)); return d; }
__device__ __forceinline__ ull mul2_(ull a, ull b){ ull d; asm("mul.rn.f32x2 %0,%1,%2;":"=l"(d):"l"(a),"l"(b)); return d; }
__device__ __forceinline__ float ex2_(float x){ float r; asm("ex2.approx.f32 %0,%1;":"=f"(r):"f"(x)); return r; }

// ---------------- device scratch ----------------
__device__ float g_Q[B_*N_*E_];          // Q proj, pre-scaled by 0.25*log2e
__device__ float g_K[B_*N_*E_];          // K proj
__device__ float g_VW[B_*N_*H_];         // v . w_force per head
__device__ float g_Wveff[H_*E_];
__device__ float g_beff[H_];
__device__ float g_part[12*2*B_*N_*16];  // [g][ms][b][n][hh][4]: den,A0,A1,A2

// ---------------- kernel 1: fold Wv with w_force ----------------
__global__ void wveff_kernel(const float* __restrict__ Wv,
                             const float* __restrict__ bv,
                             const float* __restrict__ wf)
{
    int h = blockIdx.x, e = threadIdx.x;
    float sv = 0.f;
#pragma unroll
    for (int dd = 0; dd < 16; dd++)
        sv = fmaf(wf[h*16+dd], Wv[(h*16+dd)*E_ + e], sv);
    g_Wveff[h*E_ + e] = sv;
    if (e == 0) {
        float bb = 0.f;
#pragma unroll
        for (int dd = 0; dd < 16; dd++)
            bb = fmaf(wf[h*16+dd], bv[h*16+dd], bb);
        g_beff[h] = bb;
    }
}

// ---------------- kernel 2: fused Q+K projection GEMM (f32x2, double-buffered) ----------------
// Tile 64 rows x 128 cols, 256 threads, micro 4 rows x 4 col-pairs.
// Col-pair cp = tx + 16*jp (strided -> conflict-free ull LDS).
__global__ __launch_bounds__(256,2) void qk_gemm(
    const float* __restrict__ A,
    const float* __restrict__ Wq, const float* __restrict__ bq,
    const float* __restrict__ Wk, const float* __restrict__ bk)
{
    __shared__ ull   Asd[2][16*64];    // [k][row], duplicated (a,a)
    __shared__ float Bs[2][16*132];    // [k][col], pad 132

    int t  = threadIdx.x;
    int tx = t & 15, ty = t >> 4;
    int row0 = blockIdx.y * 64;
    int col0 = blockIdx.x * 128;

    const float* __restrict__ W; const float* __restrict__ bvec;
    float scale; float* C; int cb;
    if (col0 < E_) { W = Wq; bvec = bq; scale = 0.25f*LOG2E; C = g_Q; cb = col0; }
    else           { W = Wk; bvec = bk; scale = 1.0f;        C = g_K; cb = col0 - E_; }

    // stage slot mapping
    int arow = t >> 2;            // 0..63
    int akq  = (t & 3) * 4;       // k offset
    const float* Aptr = A + (row0 + arow)*E_ + akq;
    int bcol0 = t >> 1;           // first B slot: idx=t   -> col=t>>2? use two slots
    // B: 512 slots over 2 iters: idx = it*256+t : col=idx>>2, kq=(idx&3)*4
    int bc0 = t >> 2,        bk0 = (t & 3)*4;
    int bc1 = (256+t) >> 2,  bk1 = ((256+t) & 3)*4;
    const float* Bptr0 = W + (cb + bc0)*E_ + bk0;
    const float* Bptr1 = W + (cb + bc1)*E_ + bk1;
    (void)bcol0;

    ull acc[4][4];
#pragma unroll
    for (int r = 0; r < 4; r++)
#pragma unroll
        for (int j = 0; j < 4; j++) acc[r][j] = 0ull;

    // prologue: stage k0 = 0 into buf 0
    {
        float4 va = *(const float4*)(Aptr);
        Asd[0][(akq+0)*64+arow] = pk2(va.x,va.x);
        Asd[0][(akq+1)*64+arow] = pk2(va.y,va.y);
        Asd[0][(akq+2)*64+arow] = pk2(va.z,va.z);
        Asd[0][(akq+3)*64+arow] = pk2(va.w,va.w);
        float4 vb = *(const float4*)(Bptr0);
        Bs[0][(bk0+0)*132+bc0] = vb.x; Bs[0][(bk0+1)*132+bc0] = vb.y;
        Bs[0][(bk0+2)*132+bc0] = vb.z; Bs[0][(bk0+3)*132+bc0] = vb.w;
        float4 vc = *(const float4*)(Bptr1);
        Bs[0][(bk1+0)*132+bc1] = vc.x; Bs[0][(bk1+1)*132+bc1] = vc.y;
        Bs[0][(bk1+2)*132+bc1] = vc.z; Bs[0][(bk1+3)*132+bc1] = vc.w;
    }
    __syncthreads();

    for (int s = 0; s < 48; s++) {
        int buf = s & 1;
        float4 pa, pb, pc;
        if (s < 47) {
            int k0 = (s+1)*16;
            pa = *(const float4*)(Aptr + k0);
            pb = *(const float4*)(Bptr0 + k0);
            pc = *(const float4*)(Bptr1 + k0);
        }
#pragma unroll
        for (int k = 0; k < 16; k++) {
            ull a2[4];
#pragma unroll
            for (int r = 0; r < 4; r++) a2[r] = Asd[buf][k*64 + ty*4 + r];
            const ull* bp = (const ull*)&Bs[buf][k*132];
            ull b2[4];
#pragma unroll
            for (int jp = 0; jp < 4; jp++) b2[jp] = bp[tx + 16*jp];
#pragma unroll
            for (int r = 0; r < 4; r++)
#pragma unroll
                for (int jp = 0; jp < 4; jp++)
                    acc[r][jp] = fma2_(a2[r], b2[jp], acc[r][jp]);
        }
        if (s < 47) {
            int nb = buf ^ 1;
            Asd[nb][(akq+0)*64+arow] = pk2(pa.x,pa.x);
            Asd[nb][(akq+1)*64+arow] = pk2(pa.y,pa.y);
            Asd[nb][(akq+2)*64+arow] = pk2(pa.z,pa.z);
            Asd[nb][(akq+3)*64+arow] = pk2(pa.w,pa.w);
            Bs[nb][(bk0+0)*132+bc0] = pb.x; Bs[nb][(bk0+1)*132+bc0] = pb.y;
            Bs[nb][(bk0+2)*132+bc0] = pb.z; Bs[nb][(bk0+3)*132+bc0] = pb.w;
            Bs[nb][(bk1+0)*132+bc1] = pc.x; Bs[nb][(bk1+1)*132+bc1] = pc.y;
            Bs[nb][(bk1+2)*132+bc1] = pc.z; Bs[nb][(bk1+3)*132+bc1] = pc.w;
        }
        __syncthreads();
    }

#pragma unroll
    for (int r = 0; r < 4; r++) {
        int row = row0 + ty*4 + r;
#pragma unroll
        for (int jp = 0; jp < 4; jp++) {
            int c0 = cb + 2*(tx + 16*jp);
            float v0, v1; upk2(v0, v1, acc[r][jp]);
            float2 o = make_float2(scale*(v0 + bvec[c0]), scale*(v1 + bvec[c0+1]));
            *(float2*)(C + row*E_ + c0) = o;
        }
    }
}

// ---------------- kernel 3: vw = query @ Wv_eff^T + b_eff ----------------
__global__ __launch_bounds__(768) void vw_kernel(const float* __restrict__ query)
{
    __shared__ float qrow[E_];
    int row = blockIdx.x;
    qrow[threadIdx.x] = query[row*E_ + threadIdx.x];
    __syncthreads();
    int h = threadIdx.x >> 4, lane = threadIdx.x & 15;
    const float* __restrict__ wv = &g_Wveff[h*E_];
    float sacc = 0.f;
#pragma unroll 8
    for (int j = lane; j < E_; j += 16) sacc = fmaf(qrow[j], wv[j], sacc);
#pragma unroll
    for (int o = 8; o > 0; o >>= 1) sacc += __shfl_down_sync(0xffffffffu, sacc, o, 16);
    if (lane == 0) g_VW[row*H_ + h] = sacc + g_beff[h];
}

// ---------------- kernel 4: fused attention (no-max softmax, f32x2) ----------------
// grid (12 hg, 16 ntile, b*2+ms).  256 threads: h=t&3, nq=(t>>2)&15, s=t>>6.
// Each thread: ONE packed rowpair (2 n-rows) x 4 m-cols per 16-chunk; 24 chunks.
__global__ __launch_bounds__(256,2) void attn_kernel(
    const float* __restrict__ bias, const float* __restrict__ dp,
    const int*   __restrict__ outcell)
{
    __shared__ ulonglong2 sKraw[4*130];        // h stride 260 ull
    __shared__ float  sB[4*529];               // h*529 + mc*33 + n
    __shared__ float  sDPs[3*528];             // c*528 + mc*33 + n
    __shared__ ull    sVW[16*4];               // mc*4+h, duplicated
    __shared__ float2 scomb[4][4][16][4];      // [s][h][rowpair][val]

    ull* sK = (ull*)sKraw;

    int t  = threadIdx.x;
    int h  = t & 3;
    int nq = (t >> 2) & 15;
    int s  = t >> 6;
    int g  = blockIdx.x;
    int h0 = g * 4;
    int n0 = blockIdx.y * 32;
    int bz = blockIdx.z;
    int b  = bz >> 1, ms = bz & 1;
    const int* __restrict__ oc = outcell + b*NEXP_;

    // Q rowpair, packed (row, row+1). Already *0.25*log2e.
    ull qpk[16];
    {
        const float* q0 = &g_Q[(b*N_ + n0 + nq*2)*E_ + (h0+h)*D_];
        const float* q1 = q0 + E_;
#pragma unroll
        for (int d = 0; d < 16; d++) qpk[d] = pk2(q0[d], q1[d]);
    }

    ull den = 0ull, Ac0 = 0ull, Ac1 = 0ull, Ac2 = 0ull;

#pragma unroll 1
    for (int ch = 0; ch < 24; ch++) {
        int m0 = ms*384 + ch*16;
        __syncthreads();
        // --- K (gathered, stored duplicated): 256 slots, 1 iter ---
        {
            int mc = t >> 4, q4 = t & 15;
            int hh = q4 >> 2, dg = (q4 & 3)*4;
            int m = m0 + mc;
            int r = (m < N_) ? m : oc[m - N_];
            float4 v = *(const float4*)&g_K[(b*N_ + r)*E_ + (h0+hh)*D_ + dg];
            ull* dst = &sK[hh*260 + mc*16 + dg];
            dst[0] = pk2(v.x,v.x); dst[1] = pk2(v.y,v.y);
            dst[2] = pk2(v.z,v.z); dst[3] = pk2(v.w,v.w);
        }
        // --- bias (scaled by log2e at stage time): 2048 slots, 8 iters ---
        {
            int bb = b*H_ + h0;
#pragma unroll
            for (int it = 0; it < 8; it++) {
                int idx = it*256 + t;
                int mc = idx & 15, n = (idx >> 4) & 31, hh = idx >> 9;
                sB[hh*529 + mc*33 + n] =
                    LOG2E * bias[(bb+hh)*(N_*M_) + (n0+n)*M_ + m0 + mc];
            }
        }
        // --- delta_pos: 1536 slots, 6 iters ---
#pragma unroll
        for (int it = 0; it < 6; it++) {
            int idx = it*256 + t;
            int n = idx / 48; int rem = idx - n*48;
            int mc = rem / 3; int c = rem - mc*3;
            sDPs[c*528 + mc*33 + n] = dp[((b*N_ + n0+n)*M_ + m0+mc)*3 + c];
        }
        // --- vw (gathered, duplicated) ---
        if (t < 64) {
            int mc = t >> 2, hh = t & 3;
            int m = m0 + mc;
            int r = (m < N_) ? m : oc[m - N_];
            float v = g_VW[(b*N_ + r)*H_ + h0 + hh];
            sVW[mc*4 + hh] = pk2(v, v);
        }
        __syncthreads();

        // --- compute: 4 m-cols for this thread's rowpair ---
#pragma unroll
        for (int jj = 0; jj < 4; jj++) {
            int mc = s*4 + jj;
            const ulonglong2* kp = (const ulonglong2*)&sK[h*260 + mc*16];
            int na = nq*2;
            // two parallel 8-deep chains
            ull l2a = pk2(sB[h*529 + mc*33 + na], sB[h*529 + mc*33 + na + 1]);
            ull l2b = 0ull;
            {
                ulonglong2 k0 = kp[0], k1 = kp[1];
                l2a = fma2_(qpk[0], k0.x, l2a); l2a = fma2_(qpk[1], k0.y, l2a);
                l2a = fma2_(qpk[2], k1.x, l2a); l2a = fma2_(qpk[3], k1.y, l2a);
                ulonglong2 k2 = kp[4], k3 = kp[5];
                l2b = fma2_(qpk[8],  k2.x, l2b); l2b = fma2_(qpk[9],  k2.y, l2b);
                l2b = fma2_(qpk[10], k3.x, l2b); l2b = fma2_(qpk[11], k3.y, l2b);
                ulonglong2 k4 = kp[2], k5 = kp[3];
                l2a = fma2_(qpk[4], k4.x, l2a); l2a = fma2_(qpk[5], k4.y, l2a);
                l2a = fma2_(qpk[6], k5.x, l2a); l2a = fma2_(qpk[7], k5.y, l2a);
                ulonglong2 k6 = kp[6], k7 = kp[7];
                l2b = fma2_(qpk[12], k6.x, l2b); l2b = fma2_(qpk[13], k6.y, l2b);
                l2b = fma2_(qpk[14], k7.x, l2b); l2b = fma2_(qpk[15], k7.y, l2b);
            }
            ull l2 = add2_(l2a, l2b);
            float l0, l1; upk2(l0, l1, l2);
            ull p2 = pk2(ex2_(l0), ex2_(l1));
            den = add2_(den, p2);
            ull pv = mul2_(p2, sVW[mc*4 + h]);
            Ac0 = fma2_(pv, pk2(sDPs[0*528 + mc*33 + na], sDPs[0*528 + mc*33 + na + 1]), Ac0);
            Ac1 = fma2_(pv, pk2(sDPs[1*528 + mc*33 + na], sDPs[1*528 + mc*33 + na + 1]), Ac1);
            Ac2 = fma2_(pv, pk2(sDPs[2*528 + mc*33 + na], sDPs[2*528 + mc*33 + na + 1]), Ac2);
        }
    }

    __syncthreads();
    {
        float x0, x1;
        upk2(x0, x1, den);  scomb[s][h][nq][0] = make_float2(x0, x1);
        upk2(x0, x1, Ac0);  scomb[s][h][nq][1] = make_float2(x0, x1);
        upk2(x0, x1, Ac1);  scomb[s][h][nq][2] = make_float2(x0, x1);
        upk2(x0, x1, Ac2);  scomb[s][h][nq][3] = make_float2(x0, x1);
    }
    __syncthreads();

    // reduce over s and write partials: 256 slots = (hh, rowpair, val)
    {
        int val = t & 3, rp = (t >> 2) & 15, hh = t >> 6;
        float2 a = scomb[0][hh][rp][val];
#pragma unroll
        for (int ss = 1; ss < 4; ss++) {
            float2 q = scomb[ss][hh][rp][val];
            a.x += q.x; a.y += q.y;
        }
        int n = n0 + rp*2;
        int base = ((((g*2 + ms)*2 + b)*N_ + n)*4 + hh)*4 + val;
        g_part[base]      = a.x;
        g_part[base + 16] = a.y;   // n+1 row: stride 16 floats per n
    }
}

// ---------------- kernel 5: final combine ----------------
__global__ __launch_bounds__(256) void final_kernel(float* __restrict__ out)
{
    int i = blockIdx.x*256 + threadIdx.x;   // 4 blocks -> 1024 = B*N
    int b = i >> 9, n = i & 511;
    float f0 = 0.f, f1 = 0.f, f2 = 0.f;
#pragma unroll 4
    for (int g = 0; g < 12; g++) {
#pragma unroll
        for (int hh = 0; hh < 4; hh++) {
            float4 v0 = *(const float4*)&g_part[(((g*2+0)*2 + b)*N_ + n)*16 + hh*4];
            float4 v1 = *(const float4*)&g_part[(((g*2+1)*2 + b)*N_ + n)*16 + hh*4];
            float inv = 1.0f / (v0.x + v1.x);
            f0 = fmaf(v0.y + v1.y, inv, f0);
            f1 = fmaf(v0.z + v1.z, inv, f1);
            f2 = fmaf(v0.w + v1.w, inv, f2);
        }
    }
    out[i*3+0] = f0; out[i*3+1] = f1; out[i*3+2] = f2;
}

// ---------------- launch ----------------
extern "C" void kernel_launch(void* const* d_in, const int* in_sizes, int n_in,
                              void* d_out, int out_size)
{
    const float* query = (const float*)d_in[0];
    const float* bias  = (const float*)d_in[1];
    const float* dp    = (const float*)d_in[2];
    const int*   oc    = (const int*)  d_in[3];
    const float* Wq    = (const float*)d_in[4];
    const float* bq    = (const float*)d_in[5];
    const float* Wk    = (const float*)d_in[6];
    const float* bk    = (const float*)d_in[7];
    const float* Wv    = (const float*)d_in[8];
    const float* bv    = (const float*)d_in[9];
    const float* wf    = (const float*)d_in[10];
    float* out = (float*)d_out;

    wveff_kernel<<<H_, E_>>>(Wv, bv, wf);
    qk_gemm<<<dim3(12, 16), 256>>>(query, Wq, bq, Wk, bk);
    vw_kernel<<<B_*N_, E_>>>(query);
    attn_kernel<<<dim3(12, 16, 4), 256>>>(bias, dp, oc);
    final_kernel<<<4, 256>>>(out);
}